// round 1
// baseline (speedup 1.0000x reference)
#include <cuda_runtime.h>
#include <math.h>

#define SQ 4096
#define CHN 1280
#define CC 768
#define NHEAD 8
#define HD 160
#define NCTX 77
#define NST 9
#define NSTR 8
#define LLOC 257
#define VCH 40
#define NQI_L 4

// ---------------- scratch (static device allocations, allowed) ----------------
__device__ float g_q2[2 * SQ * CHN];            // Q for batch0 (uncond) + batch1 (cond)
__device__ float g_k[NST * NCTX * CHN];
__device__ float g_v[NST * NCTX * CHN];
__device__ float g_kg[NSTR * NCTX * CHN];
__device__ float g_vg[NSTR * NCTX * CHN];
__device__ float g_kl[NSTR * LLOC * CHN];
__device__ float g_vl[NSTR * LLOC * CHN];
__device__ float g_pre[NST * SQ * CHN];         // per-stream attention output (head-merged)
__device__ float g_mix[SQ * CHN];               // fuser-premixed cond stream
__device__ float g_out2[2 * SQ * CHN];          // [pre0 ; mix] @ Wout (no bias)
__device__ float g_mraw[NSTR * NHEAD * SQ];     // gathered uncond probs
__device__ float g_mmax[NSTR];
__device__ float g_sumw[SQ];

// ---------------- helpers ----------------
__device__ __forceinline__ float wsum(float v) {
    v += __shfl_xor_sync(0xffffffffu, v, 16);
    v += __shfl_xor_sync(0xffffffffu, v, 8);
    v += __shfl_xor_sync(0xffffffffu, v, 4);
    v += __shfl_xor_sync(0xffffffffu, v, 2);
    v += __shfl_xor_sync(0xffffffffu, v, 1);
    return v;
}

// ---------------- SGEMM: C[M,N] = A[M,K] @ B[K,N], row-major -----------------
// 128x128 block tile, BK=16, 8x8 per thread, 256 threads. N must be mult of 128,
// K mult of 16 (true for all call sites: N=1280, K in {1280,768}). M guarded.
__global__ void __launch_bounds__(256) sgemm_k(const float* __restrict__ A,
                                               const float* __restrict__ B,
                                               float* __restrict__ Cm,
                                               int M, int N, int K) {
    __shared__ __align__(16) float As[16][128];
    __shared__ __align__(16) float Bs[16][132];
    int tid = threadIdx.x;
    int bx = blockIdx.x, by = blockIdx.y;
    int tx = tid & 15, ty = tid >> 4;
    float acc[8][8];
#pragma unroll
    for (int i = 0; i < 8; i++)
#pragma unroll
        for (int j = 0; j < 8; j++) acc[i][j] = 0.f;
    const int aBase = by * 128;
    const int bCol = bx * 128;
    for (int k0 = 0; k0 < K; k0 += 16) {
#pragma unroll
        for (int i = 0; i < 2; i++) {
            int idx = tid + i * 256;
            int r = idx >> 2;
            int c4 = (idx & 3) << 2;
            float4 av = make_float4(0.f, 0.f, 0.f, 0.f);
            int gr = aBase + r;
            if (gr < M) av = *reinterpret_cast<const float4*>(A + (size_t)gr * K + k0 + c4);
            As[c4][r] = av.x; As[c4 + 1][r] = av.y; As[c4 + 2][r] = av.z; As[c4 + 3][r] = av.w;
        }
#pragma unroll
        for (int i = 0; i < 2; i++) {
            int idx = tid + i * 256;
            int r = idx >> 5;
            int c4 = (idx & 31) << 2;
            float4 bv = *reinterpret_cast<const float4*>(B + (size_t)(k0 + r) * N + bCol + c4);
            Bs[r][c4] = bv.x; Bs[r][c4 + 1] = bv.y; Bs[r][c4 + 2] = bv.z; Bs[r][c4 + 3] = bv.w;
        }
        __syncthreads();
#pragma unroll
        for (int kk = 0; kk < 16; kk++) {
            float a[8], b[8];
            float4 a0 = *reinterpret_cast<const float4*>(&As[kk][ty * 8]);
            float4 a1 = *reinterpret_cast<const float4*>(&As[kk][ty * 8 + 4]);
            a[0] = a0.x; a[1] = a0.y; a[2] = a0.z; a[3] = a0.w;
            a[4] = a1.x; a[5] = a1.y; a[6] = a1.z; a[7] = a1.w;
            float4 b0 = *reinterpret_cast<const float4*>(&Bs[kk][tx * 8]);
            float4 b1 = *reinterpret_cast<const float4*>(&Bs[kk][tx * 8 + 4]);
            b[0] = b0.x; b[1] = b0.y; b[2] = b0.z; b[3] = b0.w;
            b[4] = b1.x; b[5] = b1.y; b[6] = b1.z; b[7] = b1.w;
#pragma unroll
            for (int m = 0; m < 8; m++)
#pragma unroll
                for (int n = 0; n < 8; n++) acc[m][n] += a[m] * b[n];
        }
        __syncthreads();
    }
#pragma unroll
    for (int m = 0; m < 8; m++) {
        int gr = aBase + ty * 8 + m;
        if (gr < M) {
            float* cp = Cm + (size_t)gr * N + bCol + tx * 8;
            float4 v0 = make_float4(acc[m][0], acc[m][1], acc[m][2], acc[m][3]);
            float4 v1 = make_float4(acc[m][4], acc[m][5], acc[m][6], acc[m][7]);
            *reinterpret_cast<float4*>(cp) = v0;
            *reinterpret_cast<float4*>(cp + 4) = v1;
        }
    }
}

// ------------- select ELITE global projection for valid streams --------------
__global__ void kv_select_k(const int* __restrict__ lidx) {
    int idx = blockIdx.x * 256 + threadIdx.x;
    const int tot = NSTR * NCTX * CHN;
    if (idx >= tot) return;
    int st = idx / (NCTX * CHN);   // 0..7 -> stream st+1
    if (lidx[st] >= 0) {
        g_k[NCTX * CHN + idx] = g_kg[idx];
        g_v[NCTX * CHN + idx] = g_vg[idx];
    }
}

// ---------------- global cross attention (77 keys) ----------------
// grid.x = 72 (stream*8+head), grid.y = 32 (128 queries each), 256 threads.
// k,v resident in SMEM; warp-per-query; per-warp score row in SMEM.
__global__ void __launch_bounds__(256) global_attn_k(const int* __restrict__ lidx) {
    extern __shared__ float sm[];
    float* kS = sm;                       // 77*160
    float* vS = sm + NCTX * HD;           // 77*160
    float* scB = sm + 2 * NCTX * HD;      // 8 warps * 77
    __shared__ int sIdx[8];
    int bh = blockIdx.x;
    int stream = bh >> 3, h = bh & 7;
    int tid = threadIdx.x, lane = tid & 31, w = tid >> 5;
    const float* kg = g_k + (size_t)stream * NCTX * CHN + h * HD;
    const float* vg = g_v + (size_t)stream * NCTX * CHN + h * HD;
    for (int idx = tid; idx < NCTX * HD; idx += 256) {
        int r = idx / HD, d = idx - r * HD;
        kS[idx] = kg[(size_t)r * CHN + d];
        vS[idx] = vg[(size_t)r * CHN + d];
    }
    if (tid < 8) sIdx[tid] = lidx[tid];
    __syncthreads();
    const float scale = 0.07905694150420949f;  // 1/sqrt(160)
    float* scW = scB + w * NCTX;
    const float* qb = g_q2 + (size_t)(stream == 0 ? 0 : 1) * SQ * CHN + h * HD;
    int q0 = blockIdx.y * 128;
#pragma unroll 1
    for (int t = 0; t < 16; t++) {
        int s = q0 + t * 8 + w;
        const float* qr = qb + (size_t)s * CHN;
        float ql[5];
#pragma unroll
        for (int l = 0; l < 5; l++) ql[l] = qr[lane + 32 * l];
        float lmax = -1e30f;
#pragma unroll 4
        for (int kk = 0; kk < NCTX; kk++) {
            const float* kr = kS + kk * HD;
            float p = ql[0] * kr[lane] + ql[1] * kr[lane + 32] + ql[2] * kr[lane + 64] +
                      ql[3] * kr[lane + 96] + ql[4] * kr[lane + 128];
            p = wsum(p) * scale;
            if (lane == 0) scW[kk] = p;
            lmax = fmaxf(lmax, p);     // p identical on all lanes after wsum
        }
        __syncwarp();
        float lsum = 0.f;
        for (int kk = lane; kk < NCTX; kk += 32) {
            float e = __expf(scW[kk] - lmax);
            scW[kk] = e;
            lsum += e;
        }
        lsum = wsum(lsum);
        float invs = 1.f / lsum;
        __syncwarp();
        float a0 = 0.f, a1 = 0.f, a2 = 0.f, a3 = 0.f, a4 = 0.f;
#pragma unroll 4
        for (int kk = 0; kk < NCTX; kk++) {
            float p = scW[kk];
            const float* vr = vS + kk * HD;
            a0 += p * vr[lane];       a1 += p * vr[lane + 32];
            a2 += p * vr[lane + 64];  a3 += p * vr[lane + 96];
            a4 += p * vr[lane + 128];
        }
        float* op = g_pre + ((size_t)stream * SQ + s) * CHN + h * HD;
        op[lane] = a0 * invs; op[lane + 32] = a1 * invs; op[lane + 64] = a2 * invs;
        op[lane + 96] = a3 * invs; op[lane + 128] = a4 * invs;
        if (stream == 0 && lane < 8) {
            int li = sIdx[lane];
            g_mraw[((size_t)lane * NHEAD + h) * SQ + s] = scW[li] * invs;
        }
        __syncwarp();
    }
}

// ---------------- per-instance max of the gate ----------------
__global__ void mmax_k() {
    __shared__ float red[256];
    int i = blockIdx.x;
    float mx = 0.f;
    const float* p = g_mraw + (size_t)i * NHEAD * SQ;
    for (int idx = threadIdx.x; idx < NHEAD * SQ; idx += 256) mx = fmaxf(mx, p[idx]);
    red[threadIdx.x] = mx;
    __syncthreads();
    for (int s = 128; s > 0; s >>= 1) {
        if (threadIdx.x < s) red[threadIdx.x] = fmaxf(red[threadIdx.x], red[threadIdx.x + s]);
        __syncthreads();
    }
    if (threadIdx.x == 0) g_mmax[i] = red[0];
}

// ---------------- local attention (257 keys) + gate + blend ----------------
// grid.x = 64 (inst*8+head), grid.y = 32, 1024 threads (32 warps).
// K fully SMEM-resident; V chunked through SMEM in block-wide phases.
__global__ void __launch_bounds__(1024) local_attn_k() {
    extern __shared__ float sm[];
    float* kS = sm;                           // 257*160
    float* vS = kS + LLOC * HD;               // 40*160
    float* scB = vS + VCH * HD;               // 32 warps * 257
    int ih = blockIdx.x;
    int inst = ih >> 3, h = ih & 7;
    int tid = threadIdx.x, lane = tid & 31, w = tid >> 5;
    const float* kg = g_kl + (size_t)inst * LLOC * CHN + h * HD;
    for (int idx = tid; idx < LLOC * HD; idx += 1024) {
        int r = idx / HD, d = idx - r * HD;
        kS[idx] = kg[(size_t)r * CHN + d];
    }
    __syncthreads();
    const float scale = 0.07905694150420949f;
    float minv = 1.f / g_mmax[inst];
    float* scW = scB + w * LLOC;
    int q0 = blockIdx.y * (32 * NQI_L);
#pragma unroll 1
    for (int t = 0; t < NQI_L; t++) {
        int s = q0 + t * 32 + w;
        const float* qr = g_q2 + ((size_t)SQ + s) * CHN + h * HD;   // cond batch
        float ql[5];
#pragma unroll
        for (int l = 0; l < 5; l++) ql[l] = qr[lane + 32 * l];
        float lmax = -1e30f;
#pragma unroll 4
        for (int kk = 0; kk < LLOC; kk++) {
            const float* kr = kS + kk * HD;
            float p = ql[0] * kr[lane] + ql[1] * kr[lane + 32] + ql[2] * kr[lane + 64] +
                      ql[3] * kr[lane + 96] + ql[4] * kr[lane + 128];
            p = wsum(p) * scale;
            if (lane == 0) scW[kk] = p;
            lmax = fmaxf(lmax, p);
        }
        __syncwarp();
        float lsum = 0.f;
        for (int kk = lane; kk < LLOC; kk += 32) {
            float e = __expf(scW[kk] - lmax);
            scW[kk] = e;
            lsum += e;
        }
        lsum = wsum(lsum);
        float invs = 1.f / lsum;
        float a0 = 0.f, a1 = 0.f, a2 = 0.f, a3 = 0.f, a4 = 0.f;
        __syncthreads();   // all warps done scoring; vS free to overwrite
        for (int c0 = 0; c0 < LLOC; c0 += VCH) {
            int cl = min(VCH, LLOC - c0);
            const float* vg = g_vl + ((size_t)inst * LLOC + c0) * CHN + h * HD;
            for (int idx = tid; idx < cl * HD; idx += 1024) {
                int r = idx / HD, d = idx - r * HD;
                vS[idx] = vg[(size_t)r * CHN + d];
            }
            __syncthreads();
#pragma unroll 4
            for (int kk = 0; kk < cl; kk++) {
                float p = scW[c0 + kk];
                const float* vr = vS + kk * HD;
                a0 += p * vr[lane];       a1 += p * vr[lane + 32];
                a2 += p * vr[lane + 64];  a3 += p * vr[lane + 96];
                a4 += p * vr[lane + 128];
            }
            __syncthreads();
        }
        float mv = g_mraw[((size_t)inst * NHEAD + h) * SQ + s] * minv;
        float g = 0.5f * mv * invs;
        float* op = g_pre + ((size_t)(inst + 1) * SQ + s) * CHN + h * HD;
        op[lane]       = 0.5f * op[lane]       + g * a0;
        op[lane + 32]  = 0.5f * op[lane + 32]  + g * a1;
        op[lane + 64]  = 0.5f * op[lane + 64]  + g * a2;
        op[lane + 96]  = 0.5f * op[lane + 96]  + g * a3;
        op[lane + 128] = 0.5f * op[lane + 128] + g * a4;
    }
}

// ---------------- fuser premix: mix[s] = sum_j w_j(s) * pre[1+j][s] ----------
// bilinear 1024->128->64 composes to 1/4 weights at rows {16y+3,16y+4,16y+11,16y+12}
__global__ void premix_k(const float* __restrict__ bbox) {
    int s = blockIdx.x;
    int y = s >> 6, x = s & 63;
    float wgt[8];
    wgt[0] = 1.f;
    float sw = 1.f;
    const int off[4] = {3, 4, 11, 12};
#pragma unroll
    for (int i = 0; i < 7; i++) {
        float wmin = floorf(1024.f * bbox[i * 4 + 0]);
        float hmin = floorf(1024.f * bbox[i * 4 + 1]);
        float wmax = floorf(1024.f * bbox[i * 4 + 2]);
        float hmax = floorf(1024.f * bbox[i * 4 + 3]);
        float R = 0.f, Cv = 0.f;
#pragma unroll
        for (int j = 0; j < 4; j++) {
            float yy = (float)(16 * y + off[j]);
            float xx = (float)(16 * x + off[j]);
            if (yy >= hmin && yy < hmax) R += 0.25f;
            if (xx >= wmin && xx < wmax) Cv += 0.25f;
        }
        float g = 10.f * R * Cv;
        wgt[i + 1] = g;
        sw += g;
    }
    if (threadIdx.x == 0) g_sumw[s] = sw;
    for (int c = threadIdx.x; c < CHN; c += 256) {
        float acc = 0.f;
#pragma unroll
        for (int j = 0; j < 8; j++) acc += wgt[j] * g_pre[((size_t)(1 + j) * SQ + s) * CHN + c];
        g_mix[(size_t)s * CHN + c] = acc;
    }
}

// ---------------- final: add bias, divide premixed row by (sum_w + 1e-6) -----
__global__ void final_k(const float* __restrict__ bout, float* __restrict__ out) {
    int s = blockIdx.x;
    float sw = g_sumw[s];
    float den = 1.f / (sw + 1e-6f);
    for (int c = threadIdx.x; c < CHN; c += 256) {
        float b = bout[c];
        out[(size_t)s * CHN + c] = g_out2[(size_t)s * CHN + c] + b;
        out[(size_t)(SQ + s) * CHN + c] = (g_out2[(size_t)(SQ + s) * CHN + c] + b * sw) * den;
    }
}

// ---------------- launch ----------------
extern "C" void kernel_launch(void* const* d_in, const int* in_sizes, int n_in,
                              void* d_out, int out_size) {
    const float* hs   = (const float*)d_in[0];
    const float* ctx  = (const float*)d_in[1];
    const float* lf   = (const float*)d_in[2];
    const float* bbox = (const float*)d_in[3];
    const float* Wq   = (const float*)d_in[4];
    const float* Wk   = (const float*)d_in[5];
    const float* Wv   = (const float*)d_in[6];
    const float* Wkg  = (const float*)d_in[7];
    const float* Wvg  = (const float*)d_in[8];
    const float* Wkl  = (const float*)d_in[9];
    const float* Wvl  = (const float*)d_in[10];
    const float* Wout = (const float*)d_in[11];
    const float* bout = (const float*)d_in[12];
    const int*   lidx = (const int*)d_in[13];
    float* out = (float*)d_out;

    float *q2p, *kp, *vp, *kgp, *vgp, *klp, *vlp, *prep, *mixp, *out2p;
    cudaGetSymbolAddress((void**)&q2p, g_q2);
    cudaGetSymbolAddress((void**)&kp, g_k);
    cudaGetSymbolAddress((void**)&vp, g_v);
    cudaGetSymbolAddress((void**)&kgp, g_kg);
    cudaGetSymbolAddress((void**)&vgp, g_vg);
    cudaGetSymbolAddress((void**)&klp, g_kl);
    cudaGetSymbolAddress((void**)&vlp, g_vl);
    cudaGetSymbolAddress((void**)&prep, g_pre);
    cudaGetSymbolAddress((void**)&mixp, g_mix);
    cudaGetSymbolAddress((void**)&out2p, g_out2);

    const int smemGlobal = (2 * NCTX * HD + 8 * NCTX) * sizeof(float);           // 101,024 B
    const int smemLocal  = (LLOC * HD + VCH * HD + 32 * LLOC) * sizeof(float);   // 222,976 B
    cudaFuncSetAttribute(global_attn_k, cudaFuncAttributeMaxDynamicSharedMemorySize, smemGlobal);
    cudaFuncSetAttribute(local_attn_k, cudaFuncAttributeMaxDynamicSharedMemorySize, smemLocal);

    // Q projection: only 2 distinct batches (uncond, cond)
    sgemm_k<<<dim3(10, 64), 256>>>(hs, Wq, q2p, 2 * SQ, CHN, CHN);

    // context K/V projections (merged over streams, contiguous M)
    sgemm_k<<<dim3(10, 6), 256>>>(ctx, Wk, kp, NST * NCTX, CHN, CC);
    sgemm_k<<<dim3(10, 6), 256>>>(ctx, Wv, vp, NST * NCTX, CHN, CC);
    sgemm_k<<<dim3(10, 5), 256>>>(ctx + NCTX * CC, Wkg, kgp, NSTR * NCTX, CHN, CC);
    sgemm_k<<<dim3(10, 5), 256>>>(ctx + NCTX * CC, Wvg, vgp, NSTR * NCTX, CHN, CC);
    kv_select_k<<<(NSTR * NCTX * CHN + 255) / 256, 256>>>(lidx);

    // local K/V projections
    sgemm_k<<<dim3(10, 17), 256>>>(lf, Wkl, klp, NSTR * LLOC, CHN, CC);
    sgemm_k<<<dim3(10, 17), 256>>>(lf, Wvl, vlp, NSTR * LLOC, CHN, CC);

    // attention
    global_attn_k<<<dim3(72, 32), 256, smemGlobal>>>(lidx);
    mmax_k<<<8, 256>>>();
    local_attn_k<<<dim3(64, 32), 1024, smemLocal>>>();

    // fuser premix (linear in streams) -> only 2 output-projection batches
    premix_k<<<SQ, 256>>>(bbox);
    sgemm_k<<<dim3(10, 32), 256>>>(prep, Wout, out2p, SQ, CHN, CHN);
    sgemm_k<<<dim3(10, 32), 256>>>(mixp, Wout, out2p + SQ * CHN, SQ, CHN, CHN);
    final_k<<<SQ, 256>>>(bout, out);
}

// round 2
// speedup vs baseline: 4.7899x; 4.7899x over previous
#include <cuda_runtime.h>
#include <math.h>
#include <stdint.h>

#define SQ 4096
#define CHN 1280
#define CC 768
#define NHEAD 8
#define HD 160
#define NCTX 77
#define NCTXP 80
#define NST 9
#define NSTR 8
#define LLOC 257
#define LLOCP 272

// ---------------- scratch ----------------
__device__ float g_q2[2 * SQ * CHN];
__device__ float g_k[NST * NCTX * CHN];
__device__ float g_v[NST * NCTX * CHN];
__device__ float g_kg[NSTR * NCTX * CHN];
__device__ float g_vg[NSTR * NCTX * CHN];
__device__ float g_kl[NSTR * LLOC * CHN];
__device__ float g_vl[NSTR * LLOC * CHN];
__device__ float g_WqT[CHN * CHN];
__device__ float g_WkT[CHN * CC];
__device__ float g_WvT[CHN * CC];
__device__ float g_WkgT[CHN * CC];
__device__ float g_WvgT[CHN * CC];
__device__ float g_WklT[CHN * CC];
__device__ float g_WvlT[CHN * CC];
__device__ float g_WoutT[CHN * CHN];
__device__ float g_vT[NST * CHN * NCTXP];       // per stream: [1280][80], zero-padded
__device__ float g_vlT[NSTR * CHN * LLOCP];     // per inst:   [1280][272], zero-padded
__device__ float g_scg[72 * SQ * NCTXP];        // global scores/probs
__device__ float g_scl[64 * SQ * LLOCP];        // local scores/probs
__device__ float g_pre[NST * SQ * CHN];
__device__ float g_mix[SQ * CHN];
__device__ float g_out2[2 * SQ * CHN];
__device__ float g_mraw[NSTR * NHEAD * SQ];
__device__ float g_mmax[NSTR];
__device__ float g_sumw[SQ];

__device__ const float* d_Ap[320];
__device__ const float* d_Bp[320];
__device__ float*       d_Cp[320];

// ---------------- setup: batch pointer tables ----------------
__global__ void setup_k(const float* hs, const float* ctx, const float* lf) {
    int z = threadIdx.x;
    if (z == 0) {
        d_Ap[0] = hs;                d_Bp[0] = g_WqT;   d_Cp[0] = g_q2;
        d_Ap[1] = ctx;               d_Bp[1] = g_WkT;   d_Cp[1] = g_k;
        d_Ap[2] = ctx;               d_Bp[2] = g_WvT;   d_Cp[2] = g_v;
        d_Ap[3] = ctx + NCTX * CC;   d_Bp[3] = g_WkgT;  d_Cp[3] = g_kg;
        d_Ap[4] = ctx + NCTX * CC;   d_Bp[4] = g_WvgT;  d_Cp[4] = g_vg;
        d_Ap[5] = lf;                d_Bp[5] = g_WklT;  d_Cp[5] = g_kl;
        d_Ap[6] = lf;                d_Bp[6] = g_WvlT;  d_Cp[6] = g_vl;
        d_Ap[7] = g_pre;             d_Bp[7] = g_WoutT; d_Cp[7] = g_out2;
        d_Ap[8] = g_mix;             d_Bp[8] = g_WoutT; d_Cp[8] = g_out2 + (size_t)SQ * CHN;
    }
    if (z < 72) {
        d_Ap[16 + z] = g_q2 + (z >= 8 ? (size_t)SQ * CHN : 0) + (z & 7) * HD;
        d_Bp[16 + z] = g_k + (size_t)(z >> 3) * NCTX * CHN + (z & 7) * HD;
        d_Cp[16 + z] = g_scg + (size_t)z * SQ * NCTXP;
        d_Ap[96 + z] = g_scg + (size_t)z * SQ * NCTXP;
        d_Bp[96 + z] = g_vT + (size_t)(z >> 3) * CHN * NCTXP + (z & 7) * HD * NCTXP;
        d_Cp[96 + z] = g_pre + (size_t)(z >> 3) * SQ * CHN + (z & 7) * HD;
    }
    if (z < 64) {
        d_Ap[176 + z] = g_q2 + (size_t)SQ * CHN + (z & 7) * HD;
        d_Bp[176 + z] = g_kl + (size_t)(z >> 3) * LLOC * CHN + (z & 7) * HD;
        d_Cp[176 + z] = g_scl + (size_t)z * SQ * LLOCP;
        d_Ap[240 + z] = g_scl + (size_t)z * SQ * LLOCP;
        d_Bp[240 + z] = g_vlT + (size_t)(z >> 3) * CHN * LLOCP + (z & 7) * HD * LLOCP;
        d_Cp[240 + z] = g_pre + (size_t)((z >> 3) + 1) * SQ * CHN + (z & 7) * HD;
    }
}

// ---------------- helpers ----------------
__device__ __forceinline__ uint32_t f2tf(float x) {
    uint32_t r;
    asm("cvt.rna.tf32.f32 %0, %1;" : "=r"(r) : "f"(x));
    return r;
}
__device__ __forceinline__ void cp16(float* sdst, const float* gsrc, bool p) {
    uint32_t sa = (uint32_t)__cvta_generic_to_shared(sdst);
    int sz = p ? 16 : 0;
    asm volatile("cp.async.cg.shared.global [%0], [%1], 16, %2;" :: "r"(sa), "l"(gsrc), "r"(sz));
}
#define CP_COMMIT asm volatile("cp.async.commit_group;")
__device__ __forceinline__ void mma8(float* c, const uint32_t* a, const uint32_t* b) {
    asm volatile(
        "mma.sync.aligned.m16n8k8.row.col.f32.tf32.tf32.f32 "
        "{%0,%1,%2,%3}, {%4,%5,%6,%7}, {%8,%9}, {%0,%1,%2,%3};"
        : "+f"(c[0]), "+f"(c[1]), "+f"(c[2]), "+f"(c[3])
        : "r"(a[0]), "r"(a[1]), "r"(a[2]), "r"(a[3]), "r"(b[0]), "r"(b[1]));
}
// swizzled smem offset for [128][16] tile, conflict-free fragment reads
#define SWOFF(r, c) (((r) << 4) + ((((((c) >> 2) ^ (((r) >> 1) & 3))) << 2) | ((c) & 3)))

// ---------------- batched NT tf32 GEMM: C[m][n] = sum_k A[m][k] * Bt[n][k] ----
__global__ void __launch_bounds__(256) gemm_tf32(int slot, int M, int N, int K,
                                                 int lda, int ldb, int ldc, int blend) {
    const float* Ab = d_Ap[slot + blockIdx.z];
    const float* Bb = d_Bp[slot + blockIdx.z];
    float* Cm       = d_Cp[slot + blockIdx.z];
    __shared__ __align__(16) float As[2][128 * 16];
    __shared__ __align__(16) float Bs[2][128 * 16];
    int tid = threadIdx.x, lane = tid & 31, warp = tid >> 5;
    int mBase = blockIdx.y << 7, nBase = blockIdx.x << 7;
    int mW = (warp >> 2) << 6, nW = (warp & 3) << 5;
    float acc[4][4][4];
#pragma unroll
    for (int a = 0; a < 4; a++)
#pragma unroll
        for (int b = 0; b < 4; b++)
#pragma unroll
            for (int cidx = 0; cidx < 4; cidx++) acc[a][b][cidx] = 0.f;

    const int lr = tid >> 2, lc4 = tid & 3;
    int KT = K >> 4;
    // prologue: stage 0
#pragma unroll
    for (int i = 0; i < 2; i++) {
        int r = lr + (i << 6);
        int gr = mBase + r; bool pa = gr < M; if (!pa) gr = M - 1;
        cp16(&As[0][SWOFF(r, lc4 << 2)], Ab + (size_t)gr * lda + (lc4 << 2), pa);
        int gn = nBase + r; bool pb = gn < N; if (!pb) gn = N - 1;
        cp16(&Bs[0][SWOFF(r, lc4 << 2)], Bb + (size_t)gn * ldb + (lc4 << 2), pb);
    }
    CP_COMMIT;

    for (int kt = 0; kt < KT; kt++) {
        int cur = kt & 1;
        if (kt + 1 < KT) {
            int k0 = (kt + 1) << 4, nxt = cur ^ 1;
#pragma unroll
            for (int i = 0; i < 2; i++) {
                int r = lr + (i << 6);
                int gr = mBase + r; bool pa = gr < M; if (!pa) gr = M - 1;
                cp16(&As[nxt][SWOFF(r, lc4 << 2)], Ab + (size_t)gr * lda + k0 + (lc4 << 2), pa);
                int gn = nBase + r; bool pb = gn < N; if (!pb) gn = N - 1;
                cp16(&Bs[nxt][SWOFF(r, lc4 << 2)], Bb + (size_t)gn * ldb + k0 + (lc4 << 2), pb);
            }
            CP_COMMIT;
            asm volatile("cp.async.wait_group 1;");
        } else {
            asm volatile("cp.async.wait_group 0;");
        }
        __syncthreads();
        const float* pA = As[cur];
        const float* pB = Bs[cur];
#pragma unroll
        for (int kk = 0; kk < 2; kk++) {
            int ck = (kk << 3) + (lane & 3);
            uint32_t af[4][4], bf[4][2];
#pragma unroll
            for (int mi = 0; mi < 4; mi++) {
                int r0 = mW + (mi << 4) + (lane >> 2);
                af[mi][0] = f2tf(pA[SWOFF(r0, ck)]);
                af[mi][1] = f2tf(pA[SWOFF(r0 + 8, ck)]);
                af[mi][2] = f2tf(pA[SWOFF(r0, ck + 4)]);
                af[mi][3] = f2tf(pA[SWOFF(r0 + 8, ck + 4)]);
            }
#pragma unroll
            for (int ni = 0; ni < 4; ni++) {
                int r0 = nW + (ni << 3) + (lane >> 2);
                bf[ni][0] = f2tf(pB[SWOFF(r0, ck)]);
                bf[ni][1] = f2tf(pB[SWOFF(r0, ck + 4)]);
            }
#pragma unroll
            for (int mi = 0; mi < 4; mi++)
#pragma unroll
                for (int ni = 0; ni < 4; ni++) mma8(acc[mi][ni], af[mi], bf[ni]);
        }
        __syncthreads();
    }
    // epilogue
#pragma unroll
    for (int mi = 0; mi < 4; mi++) {
        int gm = mBase + mW + (mi << 4) + (lane >> 2);
#pragma unroll
        for (int ni = 0; ni < 4; ni++) {
            int gn = nBase + nW + (ni << 3) + ((lane & 3) << 1);
            float* cc = acc[mi][ni];
            if (gm < M) {
                size_t b0 = (size_t)gm * ldc + gn;
                if (gn < N)     Cm[b0]     = blend ? 0.5f * Cm[b0]     + cc[0] : cc[0];
                if (gn + 1 < N) Cm[b0 + 1] = blend ? 0.5f * Cm[b0 + 1] + cc[1] : cc[1];
            }
            if (gm + 8 < M) {
                size_t b1 = (size_t)(gm + 8) * ldc + gn;
                if (gn < N)     Cm[b1]     = blend ? 0.5f * Cm[b1]     + cc[2] : cc[2];
                if (gn + 1 < N) Cm[b1 + 1] = blend ? 0.5f * Cm[b1 + 1] + cc[3] : cc[3];
            }
        }
    }
}

// ---------------- transpose: dst[c][r] = src[r][c], zero-fill r in [R, ldD) ---
__global__ void transpose_k(const float* __restrict__ src, float* __restrict__ dst,
                            int R, int C, int ldS, int ldD, long long sBS, long long dBS) {
    __shared__ float t[32][33];
    src += blockIdx.z * sBS;
    dst += blockIdx.z * dBS;
    int c0 = blockIdx.x << 5, r0 = blockIdx.y << 5;
    int tx = threadIdx.x, ty = threadIdx.y;
#pragma unroll
    for (int j = 0; j < 4; j++) {
        int rr = r0 + ty + j * 8, cc = c0 + tx;
        t[ty + j * 8][tx] = (rr < R && cc < C) ? src[(size_t)rr * ldS + cc] : 0.f;
    }
    __syncthreads();
#pragma unroll
    for (int j = 0; j < 4; j++) {
        int cc = c0 + ty + j * 8, rr = r0 + tx;
        if (cc < C && rr < ldD) dst[(size_t)cc * ldD + rr] = t[tx][ty + j * 8];
    }
}

// ---------------- ELITE K/V select ----------------
__global__ void kv_select_k(const int* __restrict__ lidx) {
    int idx = blockIdx.x * 256 + threadIdx.x;
    const int tot = NSTR * NCTX * CHN;
    if (idx >= tot) return;
    int st = idx / (NCTX * CHN);
    if (lidx[st] >= 0) {
        g_k[NCTX * CHN + idx] = g_kg[idx];
        g_v[NCTX * CHN + idx] = g_vg[idx];
    }
}

// ---------------- global softmax (77 keys) + gate gather ----------------
__global__ void __launch_bounds__(256) softmax_g_k(const int* __restrict__ lidx) {
    __shared__ int sidx[8];
    if (threadIdx.x < 8) sidx[threadIdx.x] = lidx[threadIdx.x];
    __syncthreads();
    int bh = blockIdx.y;
    int w = threadIdx.x >> 5, lane = threadIdx.x & 31;
    int s = blockIdx.x * 8 + w;
    float* row = g_scg + ((size_t)bh * SQ + s) * NCTXP;
    const float scale = 0.07905694150420949f;
    float x0 = row[lane];
    float x1 = row[32 + lane];
    float x2 = (lane < 13) ? row[64 + lane] : -1e30f;
    float m = fmaxf(fmaxf(x0, x1), x2);
#pragma unroll
    for (int o = 16; o; o >>= 1) m = fmaxf(m, __shfl_xor_sync(0xffffffffu, m, o));
    float e0 = __expf((x0 - m) * scale);
    float e1 = __expf((x1 - m) * scale);
    float e2 = (lane < 13) ? __expf((x2 - m) * scale) : 0.f;
    float ss = e0 + e1 + e2;
#pragma unroll
    for (int o = 16; o; o >>= 1) ss += __shfl_xor_sync(0xffffffffu, ss, o);
    float inv = 1.f / ss;
    e0 *= inv; e1 *= inv; e2 *= inv;
    row[lane] = e0;
    row[32 + lane] = e1;
    if (lane < 16) row[64 + lane] = (lane < 13) ? e2 : 0.f;
    if (bh < 8) {
#pragma unroll
        for (int i = 0; i < 8; i++) {
            int li = sidx[i];
            int seg = li >> 5, src = li & 31;
            float cand = (seg == 0) ? e0 : ((seg == 1) ? e1 : e2);
            float v = __shfl_sync(0xffffffffu, cand, src);
            if (lane == 0) g_mraw[((size_t)i * NHEAD + bh) * SQ + s] = v;
        }
    }
}

// ---------------- per-instance gate max ----------------
__global__ void mmax_k() {
    __shared__ float red[256];
    int i = blockIdx.x;
    float mx = 0.f;
    const float* p = g_mraw + (size_t)i * NHEAD * SQ;
    for (int idx = threadIdx.x; idx < NHEAD * SQ; idx += 256) mx = fmaxf(mx, p[idx]);
    red[threadIdx.x] = mx;
    __syncthreads();
    for (int s = 128; s > 0; s >>= 1) {
        if (threadIdx.x < s) red[threadIdx.x] = fmaxf(red[threadIdx.x], red[threadIdx.x + s]);
        __syncthreads();
    }
    if (threadIdx.x == 0) g_mmax[i] = red[0];
}

// ---------------- local softmax (257 keys), gate folded ----------------
__global__ void __launch_bounds__(256) softmax_l_k() {
    int z = blockIdx.y;  // inst*8 + h
    int w = threadIdx.x >> 5, lane = threadIdx.x & 31;
    int s = blockIdx.x * 8 + w;
    float* row = g_scl + ((size_t)z * SQ + s) * LLOCP;
    const float scale = 0.07905694150420949f;
    float x[9];
#pragma unroll
    for (int j = 0; j < 9; j++) {
        int c = j * 32 + lane;
        x[j] = (c < LLOC) ? row[c] : -1e30f;
    }
    float m = -1e30f;
#pragma unroll
    for (int j = 0; j < 9; j++) m = fmaxf(m, x[j]);
#pragma unroll
    for (int o = 16; o; o >>= 1) m = fmaxf(m, __shfl_xor_sync(0xffffffffu, m, o));
    float ss = 0.f;
#pragma unroll
    for (int j = 0; j < 9; j++) {
        int c = j * 32 + lane;
        x[j] = (c < LLOC) ? __expf((x[j] - m) * scale) : 0.f;
        ss += x[j];
    }
#pragma unroll
    for (int o = 16; o; o >>= 1) ss += __shfl_xor_sync(0xffffffffu, ss, o);
    float gate = 0.5f * g_mraw[(size_t)z * SQ + s] / g_mmax[z >> 3];
    float f = gate / ss;
#pragma unroll
    for (int j = 0; j < 9; j++) {
        int c = j * 32 + lane;
        if (c < LLOCP) row[c] = x[j] * f;
    }
}

// ---------------- fuser premix ----------------
__global__ void premix_k(const float* __restrict__ bbox) {
    int s = blockIdx.x;
    int y = s >> 6, x = s & 63;
    float wgt[8];
    wgt[0] = 1.f;
    float sw = 1.f;
    const int off[4] = {3, 4, 11, 12};
#pragma unroll
    for (int i = 0; i < 7; i++) {
        float wmin = floorf(1024.f * bbox[i * 4 + 0]);
        float hmin = floorf(1024.f * bbox[i * 4 + 1]);
        float wmax = floorf(1024.f * bbox[i * 4 + 2]);
        float hmax = floorf(1024.f * bbox[i * 4 + 3]);
        float R = 0.f, Cv = 0.f;
#pragma unroll
        for (int j = 0; j < 4; j++) {
            float yy = (float)(16 * y + off[j]);
            float xx = (float)(16 * x + off[j]);
            if (yy >= hmin && yy < hmax) R += 0.25f;
            if (xx >= wmin && xx < wmax) Cv += 0.25f;
        }
        float g = 10.f * R * Cv;
        wgt[i + 1] = g;
        sw += g;
    }
    if (threadIdx.x == 0) g_sumw[s] = sw;
    for (int c = threadIdx.x; c < CHN; c += 256) {
        float acc = 0.f;
#pragma unroll
        for (int j = 0; j < 8; j++) acc += wgt[j] * g_pre[((size_t)(1 + j) * SQ + s) * CHN + c];
        g_mix[(size_t)s * CHN + c] = acc;
    }
}

// ---------------- final ----------------
__global__ void final_k(const float* __restrict__ bout, float* __restrict__ out) {
    int s = blockIdx.x;
    float sw = g_sumw[s];
    float den = 1.f / (sw + 1e-6f);
    for (int c = threadIdx.x; c < CHN; c += 256) {
        float b = bout[c];
        out[(size_t)s * CHN + c] = g_out2[(size_t)s * CHN + c] + b;
        out[(size_t)(SQ + s) * CHN + c] = (g_out2[(size_t)(SQ + s) * CHN + c] + b * sw) * den;
    }
}

// ---------------- launch ----------------
extern "C" void kernel_launch(void* const* d_in, const int* in_sizes, int n_in,
                              void* d_out, int out_size) {
    const float* hs   = (const float*)d_in[0];
    const float* ctx  = (const float*)d_in[1];
    const float* lf   = (const float*)d_in[2];
    const float* bbox = (const float*)d_in[3];
    const float* Wq   = (const float*)d_in[4];
    const float* Wk   = (const float*)d_in[5];
    const float* Wv   = (const float*)d_in[6];
    const float* Wkg  = (const float*)d_in[7];
    const float* Wvg  = (const float*)d_in[8];
    const float* Wkl  = (const float*)d_in[9];
    const float* Wvl  = (const float*)d_in[10];
    const float* Wout = (const float*)d_in[11];
    const float* bout = (const float*)d_in[12];
    const int*   lidx = (const int*)d_in[13];
    float* out = (float*)d_out;

    float *WqT, *WkT, *WvT, *WkgT, *WvgT, *WklT, *WvlT, *WoutT, *vp, *vTp, *vlp, *vlTp;
    cudaGetSymbolAddress((void**)&WqT, g_WqT);
    cudaGetSymbolAddress((void**)&WkT, g_WkT);
    cudaGetSymbolAddress((void**)&WvT, g_WvT);
    cudaGetSymbolAddress((void**)&WkgT, g_WkgT);
    cudaGetSymbolAddress((void**)&WvgT, g_WvgT);
    cudaGetSymbolAddress((void**)&WklT, g_WklT);
    cudaGetSymbolAddress((void**)&WvlT, g_WvlT);
    cudaGetSymbolAddress((void**)&WoutT, g_WoutT);
    cudaGetSymbolAddress((void**)&vp, g_v);
    cudaGetSymbolAddress((void**)&vTp, g_vT);
    cudaGetSymbolAddress((void**)&vlp, g_vl);
    cudaGetSymbolAddress((void**)&vlTp, g_vlT);

    dim3 tb(32, 8);
    setup_k<<<1, 256>>>(hs, ctx, lf);

    // weight transposes (NT GEMM needs Bt = W^T, row-major [N][K])
    transpose_k<<<dim3(40, 40, 1), tb>>>(Wq, WqT, CHN, CHN, CHN, CHN, 0, 0);
    transpose_k<<<dim3(40, 24, 1), tb>>>(Wk, WkT, CC, CHN, CHN, CC, 0, 0);
    transpose_k<<<dim3(40, 24, 1), tb>>>(Wv, WvT, CC, CHN, CHN, CC, 0, 0);
    transpose_k<<<dim3(40, 24, 1), tb>>>(Wkg, WkgT, CC, CHN, CHN, CC, 0, 0);
    transpose_k<<<dim3(40, 24, 1), tb>>>(Wvg, WvgT, CC, CHN, CHN, CC, 0, 0);
    transpose_k<<<dim3(40, 24, 1), tb>>>(Wkl, WklT, CC, CHN, CHN, CC, 0, 0);
    transpose_k<<<dim3(40, 24, 1), tb>>>(Wvl, WvlT, CC, CHN, CHN, CC, 0, 0);
    transpose_k<<<dim3(40, 40, 1), tb>>>(Wout, WoutT, CHN, CHN, CHN, CHN, 0, 0);

    // projections
    gemm_tf32<<<dim3(10, 64, 1), 256>>>(0, 2 * SQ, CHN, CHN, CHN, CHN, CHN, 0);      // Q (2 batches)
    gemm_tf32<<<dim3(10, 6, 1), 256>>>(1, NST * NCTX, CHN, CC, CC, CC, CHN, 0);      // K
    gemm_tf32<<<dim3(10, 6, 1), 256>>>(2, NST * NCTX, CHN, CC, CC, CC, CHN, 0);      // V
    gemm_tf32<<<dim3(10, 5, 1), 256>>>(3, NSTR * NCTX, CHN, CC, CC, CC, CHN, 0);     // Kg
    gemm_tf32<<<dim3(10, 5, 1), 256>>>(4, NSTR * NCTX, CHN, CC, CC, CC, CHN, 0);     // Vg
    gemm_tf32<<<dim3(10, 17, 1), 256>>>(5, NSTR * LLOC, CHN, CC, CC, CC, CHN, 0);    // Kl
    gemm_tf32<<<dim3(10, 17, 1), 256>>>(6, NSTR * LLOC, CHN, CC, CC, CC, CHN, 0);    // Vl
    kv_select_k<<<(NSTR * NCTX * CHN + 255) / 256, 256>>>(lidx);

    // V transposes for PV GEMMs (after kv_select)
    transpose_k<<<dim3(40, 3, NST), tb>>>(vp, vTp, NCTX, CHN, CHN, NCTXP,
                                          (long long)NCTX * CHN, (long long)CHN * NCTXP);
    transpose_k<<<dim3(40, 9, NSTR), tb>>>(vlp, vlTp, LLOC, CHN, CHN, LLOCP,
                                           (long long)LLOC * CHN, (long long)CHN * LLOCP);

    // global attention
    gemm_tf32<<<dim3(1, 32, 72), 256>>>(16, SQ, NCTX, HD, CHN, CHN, NCTXP, 0);       // scores
    softmax_g_k<<<dim3(512, 72), 256>>>(lidx);
    mmax_k<<<8, 256>>>();
    gemm_tf32<<<dim3(2, 32, 72), 256>>>(96, SQ, HD, NCTXP, NCTXP, NCTXP, CHN, 0);    // PV

    // local attention
    gemm_tf32<<<dim3(3, 32, 64), 256>>>(176, SQ, LLOC, HD, CHN, CHN, LLOCP, 0);      // scores
    softmax_l_k<<<dim3(512, 64), 256>>>();
    gemm_tf32<<<dim3(2, 32, 64), 256>>>(240, SQ, HD, LLOCP, LLOCP, LLOCP, CHN, 1);   // PV + blend

    // fuser premix + output projection
    premix_k<<<SQ, 256>>>(bbox);
    gemm_tf32<<<dim3(10, 32, 1), 256>>>(7, SQ, CHN, CHN, CHN, CHN, CHN, 0);
    gemm_tf32<<<dim3(10, 32, 1), 256>>>(8, SQ, CHN, CHN, CHN, CHN, CHN, 0);
    final_k<<<SQ, 256>>>(bout, out);
}